// round 6
// baseline (speedup 1.0000x reference)
#include <cuda_runtime.h>
#include <math.h>

#define NN 20000
#define HH 512
#define KK 128
#define EMAX 340000
#define NITER 11
#define NSPLIT 25
#define CHUNK 800
#define NDB 313      // ceil(20000/64) dist blocks
#define NCB 157      // ceil(20000/128) colsum blocks

// ---------------- device scratch (static, no allocation) ----------------
__device__ int   g_deg_out[NN], g_deg_in[NN];
__device__ float g_inv_out[NN], g_inv_in[NN];
__device__ int   g_rowptr[NN + 1], g_cursor[NN];
__device__ int   g_colsrc[EMAX];
__device__ float g_agg[(size_t)NN * HH];
__device__ float g_hid[(size_t)NN * HH];
__device__ float g_pos[(size_t)NN * HH];
__device__ float g_neg[(size_t)NN * HH];
__device__ float g_data[(size_t)NN * HH];
__device__ float g_r[(size_t)NN * KK];
__device__ float g_mu[KK * HH], g_munorm[KK * HH];
__device__ float g_muacc_part[(size_t)NSPLIT * KK * HH];
__device__ float g_colsum_part[NDB * KK];
__device__ float g_colsum[KK];
__device__ float g_cspart[NCB * HH];
__device__ float g_gs[HH], g_ws[HH];
__device__ float g_partial[625];

__device__ __forceinline__ float splus(float x) {
    return (x > 0.f) ? (x + log1pf(expf(-x))) : log1pf(expf(x));
}
__device__ __forceinline__ float sigm(float x) { return 1.f / (1.f + expf(-x)); }

// ---------------- graph setup ----------------
__global__ void k_init() {
    int i = blockIdx.x * blockDim.x + threadIdx.x;
    if (i < NN) { g_deg_out[i] = 0; g_deg_in[i] = 0; }
}

__global__ void k_count(const int* __restrict__ src, const int* __restrict__ dst, int E) {
    int e = blockIdx.x * blockDim.x + threadIdx.x;
    if (e < E) {
        atomicAdd(&g_deg_out[src[e]], 1);
        atomicAdd(&g_deg_in[dst[e]], 1);
    }
}

// single block: inv-degree factors + exclusive scan of in-degrees -> CSR row_ptr
__global__ void k_prep() {
    int t = threadIdx.x;
    for (int i = t; i < NN; i += 1024) {
        g_inv_out[i] = rsqrtf((float)max(g_deg_out[i], 1));
        g_inv_in[i]  = rsqrtf((float)max(g_deg_in[i], 1));
    }
    __syncthreads();
    __shared__ int ssum[1024];
    const int CH = (NN + 1023) / 1024;   // 20
    int b = t * CH, e = min(b + CH, NN);
    int s = 0;
    for (int i = b; i < e; i++) s += g_deg_in[i];
    ssum[t] = s;
    __syncthreads();
    for (int off = 1; off < 1024; off <<= 1) {
        int v = (t >= off) ? ssum[t - off] : 0;
        __syncthreads();
        ssum[t] += v;
        __syncthreads();
    }
    int run = (t == 0) ? 0 : ssum[t - 1];
    for (int i = b; i < e; i++) {
        g_rowptr[i] = run; g_cursor[i] = run;
        run += g_deg_in[i];
    }
    if (t == 1023) g_rowptr[NN] = ssum[1023];
}

__global__ void k_fillcsr(const int* __restrict__ src, const int* __restrict__ dst, int E) {
    int e = blockIdx.x * blockDim.x + threadIdx.x;
    if (e < E) {
        int p = atomicAdd(&g_cursor[dst[e]], 1);
        g_colsrc[p] = src[e];
    }
}

// ---------------- GCN aggregation: out[i] = inv_in[i] * sum_{e:dst=i} inv_out[s]*X[map(s)]
__global__ void __launch_bounds__(128) k_aggregate(const float* __restrict__ X,
                                                   const int* __restrict__ perm,
                                                   float* __restrict__ out) {
    int i = blockIdx.x;
    int t = threadIdx.x;   // 128 threads, one float4 each over 512 cols
    int s0 = g_rowptr[i], s1 = g_rowptr[i + 1];
    float ax = 0.f, ay = 0.f, az = 0.f, aw = 0.f;
    for (int e = s0; e < s1; e++) {
        int s = g_colsrc[e];
        float w = g_inv_out[s];
        int row = perm ? perm[s] : s;
        float4 v = ((const float4*)(X + (size_t)row * HH))[t];
        ax = fmaf(w, v.x, ax); ay = fmaf(w, v.y, ay);
        az = fmaf(w, v.z, az); aw = fmaf(w, v.w, aw);
    }
    float wi = g_inv_in[i];
    ((float4*)(out + (size_t)i * HH))[t] = make_float4(ax * wi, ay * wi, az * wi, aw * wi);
}

// ---------------- dense GEMM: C[M,512] = A[M,512] @ W[512,512] + bias (opt relu)
__global__ void __launch_bounds__(256) k_gemm(const float* __restrict__ A,
                                              const float* __restrict__ W,
                                              const float* __restrict__ bias,
                                              float* __restrict__ C, int relu) {
    __shared__ __align__(16) float As[8][132];
    __shared__ __align__(16) float Bs[8][128];
    int tid = threadIdx.x;
    int bm = blockIdx.x * 128, bn = blockIdx.y * 128;
    int tx = tid & 15, ty = tid >> 4;
    float acc[8][8];
#pragma unroll
    for (int i = 0; i < 8; i++)
#pragma unroll
        for (int j = 0; j < 8; j++) acc[i][j] = 0.f;

    int lr = tid >> 1, lc = (tid & 1) * 4;
    int bkr = tid >> 5, bc4 = (tid & 31) * 4;
    int arow = bm + lr;
    const float* Aptr = A + (size_t)arow * HH + lc;
    const float* Wptr = W + (size_t)bkr * HH + bn + bc4;

    for (int k0 = 0; k0 < HH; k0 += 8) {
        float4 av = make_float4(0.f, 0.f, 0.f, 0.f);
        if (arow < NN) av = *(const float4*)(Aptr + k0);
        As[lc + 0][lr] = av.x; As[lc + 1][lr] = av.y;
        As[lc + 2][lr] = av.z; As[lc + 3][lr] = av.w;
        *(float4*)&Bs[bkr][bc4] = *(const float4*)(Wptr + (size_t)k0 * HH);
        __syncthreads();
#pragma unroll
        for (int kk = 0; kk < 8; kk++) {
            float4 a0 = *(float4*)&As[kk][ty * 8];
            float4 a1 = *(float4*)&As[kk][ty * 8 + 4];
            float4 b0 = *(float4*)&Bs[kk][tx * 8];
            float4 b1 = *(float4*)&Bs[kk][tx * 8 + 4];
            float aa[8] = {a0.x, a0.y, a0.z, a0.w, a1.x, a1.y, a1.z, a1.w};
            float bb[8] = {b0.x, b0.y, b0.z, b0.w, b1.x, b1.y, b1.z, b1.w};
#pragma unroll
            for (int i = 0; i < 8; i++)
#pragma unroll
                for (int j = 0; j < 8; j++)
                    acc[i][j] = fmaf(aa[i], bb[j], acc[i][j]);
        }
        __syncthreads();
    }
#pragma unroll
    for (int i = 0; i < 8; i++) {
        int row = bm + ty * 8 + i;
        if (row < NN) {
#pragma unroll
            for (int j = 0; j < 8; j++) {
                float v = acc[i][j] + bias[bn + tx * 8 + j];
                if (relu) v = fmaxf(v, 0.f);
                C[(size_t)row * HH + bn + tx * 8 + j] = v;
            }
        }
    }
}

// ---------------- graph summary: column sum partials then sigmoid(mean) ----------------
__global__ void __launch_bounds__(512) k_colsum_p1(const float* __restrict__ P) {
    int b = blockIdx.x, t = threadIdx.x;
    int r0 = b * 128, r1 = min(r0 + 128, NN);
    float s = 0.f;
    for (int r = r0; r < r1; r++) s += P[(size_t)r * HH + t];
    g_cspart[b * HH + t] = s;
}

__global__ void __launch_bounds__(512) k_gs() {
    int t = threadIdx.x;
    float s = 0.f;
    for (int b = 0; b < NCB; b++) s += g_cspart[b * HH + t];
    g_gs[t] = sigm(s * (1.0f / NN));
}

__global__ void __launch_bounds__(256) k_ws(const float* __restrict__ dW) {
    int t = threadIdx.x;
    int w = t >> 5, l = t & 31;
    int row = blockIdx.x * 8 + w;
    float s = 0.f;
#pragma unroll
    for (int q = 0; q < 16; q++) {
        int j = q * 32 + l;
        s += dW[(size_t)row * HH + j] * g_gs[j];
    }
#pragma unroll
    for (int off = 16; off; off >>= 1) s += __shfl_xor_sync(0xffffffffu, s, off);
    if (l == 0) g_ws[row] = s;
}

// ---------------- row normalize ----------------
__global__ void __launch_bounds__(128) k_rownorm(const float* __restrict__ in,
                                                 float* __restrict__ out, float eps) {
    int i = blockIdx.x, t = threadIdx.x;
    float4 v = ((const float4*)(in + (size_t)i * HH))[t];
    float ss = v.x * v.x + v.y * v.y + v.z * v.z + v.w * v.w;
#pragma unroll
    for (int off = 16; off; off >>= 1) ss += __shfl_xor_sync(0xffffffffu, ss, off);
    __shared__ float sw[4];
    if ((t & 31) == 0) sw[t >> 5] = ss;
    __syncthreads();
    float inv = 1.f / (sqrtf(sw[0] + sw[1] + sw[2] + sw[3]) + eps);
    ((float4*)(out + (size_t)i * HH))[t] =
        make_float4(v.x * inv, v.y * inv, v.z * inv, v.w * inv);
}

__global__ void k_copy(const float* __restrict__ s, float* __restrict__ d, int n) {
    int i = blockIdx.x * blockDim.x + threadIdx.x;
    if (i < n) d[i] = s[i];
}

// ---------------- fused dist + beta-softmax + colsum: r = softmax(100 * data@munorm^T)
__global__ void __launch_bounds__(256) k_dist() {
    __shared__ __align__(16) float As[16][68];
    __shared__ __align__(16) float Bs[16][132];
    __shared__ __align__(16) float sd[64][132];
    int tid = threadIdx.x;
    int n0 = blockIdx.x * 64;
    int rows_valid = min(64, NN - n0);
    int tx = tid & 15, ty = tid >> 4;
    float acc[4][8];
#pragma unroll
    for (int i = 0; i < 4; i++)
#pragma unroll
        for (int j = 0; j < 8; j++) acc[i][j] = 0.f;

    int ar = tid >> 2, ac4 = (tid & 3) * 4;
    bool avalid = (n0 + ar) < NN;
    const float* aptr = g_data + (size_t)(n0 + ar) * HH + ac4;

    for (int k0 = 0; k0 < HH; k0 += 16) {
        float4 av = avalid ? *(const float4*)(aptr + k0) : make_float4(0.f, 0.f, 0.f, 0.f);
        As[ac4 + 0][ar] = av.x; As[ac4 + 1][ar] = av.y;
        As[ac4 + 2][ar] = av.z; As[ac4 + 3][ar] = av.w;
#pragma unroll
        for (int l = 0; l < 2; l++) {
            int idx = tid + l * 256;
            int kc = idx >> 2, c4 = (idx & 3) * 4;
            float4 bv = *(const float4*)(g_munorm + (size_t)kc * HH + k0 + c4);
            Bs[c4 + 0][kc] = bv.x; Bs[c4 + 1][kc] = bv.y;
            Bs[c4 + 2][kc] = bv.z; Bs[c4 + 3][kc] = bv.w;
        }
        __syncthreads();
#pragma unroll
        for (int kk = 0; kk < 16; kk++) {
            float4 a = *(float4*)&As[kk][ty * 4];
            float4 b0 = *(float4*)&Bs[kk][tx * 8];
            float4 b1 = *(float4*)&Bs[kk][tx * 8 + 4];
            float aa[4] = {a.x, a.y, a.z, a.w};
            float bb[8] = {b0.x, b0.y, b0.z, b0.w, b1.x, b1.y, b1.z, b1.w};
#pragma unroll
            for (int i = 0; i < 4; i++)
#pragma unroll
                for (int j = 0; j < 8; j++)
                    acc[i][j] = fmaf(aa[i], bb[j], acc[i][j]);
        }
        __syncthreads();
    }
#pragma unroll
    for (int i = 0; i < 4; i++)
#pragma unroll
        for (int j = 0; j < 8; j++)
            sd[ty * 4 + i][tx * 8 + j] = acc[i][j];
    __syncthreads();

    // row softmax with temp 100: 4 threads per row, 32 cols each
    int r = tid >> 2, g = tid & 3;
    if (r < rows_valid) {
        float m = -1e30f;
#pragma unroll
        for (int q = 0; q < 32; q++) m = fmaxf(m, sd[r][g + 4 * q]);
        m = fmaxf(m, __shfl_xor_sync(0xffffffffu, m, 1, 4));
        m = fmaxf(m, __shfl_xor_sync(0xffffffffu, m, 2, 4));
        float s = 0.f;
#pragma unroll
        for (int q = 0; q < 32; q++) {
            float e = expf(100.0f * (sd[r][g + 4 * q] - m));
            sd[r][g + 4 * q] = e;
            s += e;
        }
        s += __shfl_xor_sync(0xffffffffu, s, 1, 4);
        s += __shfl_xor_sync(0xffffffffu, s, 2, 4);
        float inv = 1.f / s;
#pragma unroll
        for (int q = 0; q < 32; q++) sd[r][g + 4 * q] *= inv;
    }
    __syncthreads();

    // coalesced r write
    for (int q = 0; q < 32; q++) {
        int idx = tid + 256 * q;
        int row = idx >> 7, col = idx & 127;
        if (row < rows_valid) g_r[(size_t)(n0 + row) * KK + col] = sd[row][col];
    }
    // per-block column sums (deterministic partials)
    if (tid < 128) {
        float s = 0.f;
        for (int row = 0; row < rows_valid; row++) s += sd[row][tid];
        g_colsum_part[blockIdx.x * KK + tid] = s;
    }
}

__global__ void k_colsum_red() {
    int t = threadIdx.x;   // 128
    float s = 0.f;
    for (int b = 0; b < NDB; b++) s += g_colsum_part[b * KK + t];
    g_colsum[t] = s;
}

// ---------------- muacc partial GEMM: part[split] = r_chunk^T @ data_chunk
__global__ void __launch_bounds__(256) k_mu() {
    __shared__ __align__(16) float As[16][128];   // r[n][c]
    __shared__ __align__(16) float Bs[16][64];    // data[n][col]
    int tid = threadIdx.x;
    int colbase = blockIdx.x * 64;
    int split = blockIdx.y;
    int nbase = split * CHUNK;
    int tx = tid & 15, ty = tid >> 4;
    float acc[8][4];
#pragma unroll
    for (int i = 0; i < 8; i++)
#pragma unroll
        for (int j = 0; j < 4; j++) acc[i][j] = 0.f;

    int akk = tid >> 4, ac = (tid & 15) * 8;   // As: 2 float4
    int bkk = tid >> 4, bc = (tid & 15) * 4;   // Bs: 1 float4

    for (int n0 = nbase; n0 < nbase + CHUNK; n0 += 16) {
        *(float4*)&As[akk][ac]     = *(const float4*)(g_r + (size_t)(n0 + akk) * KK + ac);
        *(float4*)&As[akk][ac + 4] = *(const float4*)(g_r + (size_t)(n0 + akk) * KK + ac + 4);
        *(float4*)&Bs[bkk][bc]     = *(const float4*)(g_data + (size_t)(n0 + bkk) * HH + colbase + bc);
        __syncthreads();
#pragma unroll
        for (int kk = 0; kk < 16; kk++) {
            float4 b = *(float4*)&Bs[kk][tx * 4];
            float4 a0 = *(float4*)&As[kk][ty * 8];
            float4 a1 = *(float4*)&As[kk][ty * 8 + 4];
            float aa[8] = {a0.x, a0.y, a0.z, a0.w, a1.x, a1.y, a1.z, a1.w};
            float bb[4] = {b.x, b.y, b.z, b.w};
#pragma unroll
            for (int i = 0; i < 8; i++)
#pragma unroll
                for (int j = 0; j < 4; j++)
                    acc[i][j] = fmaf(aa[i], bb[j], acc[i][j]);
        }
        __syncthreads();
    }
#pragma unroll
    for (int i = 0; i < 8; i++) {
        int c = ty * 8 + i;
#pragma unroll
        for (int j = 0; j < 4; j++)
            g_muacc_part[((size_t)split * KK + c) * HH + colbase + tx * 4 + j] = acc[i][j];
    }
}

__global__ void __launch_bounds__(256) k_mu_update() {
    int e = blockIdx.x * 256 + threadIdx.x;   // 65536 total
    int c = e >> 9, j = e & 511;
    float s = 0.f;
#pragma unroll 5
    for (int sp = 0; sp < NSPLIT; sp++)
        s += g_muacc_part[((size_t)sp * KK + c) * HH + j];
    g_mu[c * HH + j] = s / g_colsum[c];
}

// ---------------- fused epilogue: cs = sigmoid(r@mu); dots + softplus means ----------------
__global__ void __launch_bounds__(256) k_final() {
    __shared__ __align__(16) float r_s[32][128];
    __shared__ __align__(16) float mu_s[128][36];
    __shared__ float ws_s[HH];
    __shared__ float contrib[32];
    int tid = threadIdx.x;
    int n0 = blockIdx.x * 32;
    // load r rows
#pragma unroll
    for (int q = 0; q < 4; q++) {
        int i4 = tid + 256 * q;                 // 1024 float4s = 32*128/4
        int row = i4 >> 5, cp = (i4 & 31) * 4;
        *(float4*)&r_s[row][cp] = *(const float4*)(g_r + (size_t)(n0 + row) * KK + cp);
    }
    ws_s[tid] = g_ws[tid];
    ws_s[tid + 256] = g_ws[tid + 256];

    int node = tid >> 3, cg = (tid & 7) * 4;
    float pc = 0.f, nc = 0.f, pg = 0.f, ng = 0.f;

    for (int tile = 0; tile < 16; tile++) {
        __syncthreads();
        // load mu tile [128 x 32]
#pragma unroll
        for (int q = 0; q < 4; q++) {
            int i4 = tid + 256 * q;             // 1024 float4s
            int k = i4 >> 3, cp = (i4 & 7) * 4;
            *(float4*)&mu_s[k][cp] = *(const float4*)(g_mu + (size_t)k * HH + tile * 32 + cp);
        }
        __syncthreads();
        float c0 = 0.f, c1 = 0.f, c2 = 0.f, c3 = 0.f;
#pragma unroll 8
        for (int k = 0; k < 128; k++) {
            float rv = r_s[node][k];
            float4 m = *(float4*)&mu_s[k][cg];
            c0 = fmaf(rv, m.x, c0); c1 = fmaf(rv, m.y, c1);
            c2 = fmaf(rv, m.z, c2); c3 = fmaf(rv, m.w, c3);
        }
        int col = tile * 32 + cg;
        float4 p = *(const float4*)(g_pos + (size_t)(n0 + node) * HH + col);
        float4 nn = *(const float4*)(g_neg + (size_t)(n0 + node) * HH + col);
        float4 w = *(float4*)&ws_s[col];
        float s0 = sigm(c0), s1 = sigm(c1), s2 = sigm(c2), s3 = sigm(c3);
        pc += s0 * p.x + s1 * p.y + s2 * p.z + s3 * p.w;
        nc += s0 * nn.x + s1 * nn.y + s2 * nn.z + s3 * nn.w;
        pg += p.x * w.x + p.y * w.y + p.z * w.z + p.w * w.w;
        ng += nn.x * w.x + nn.y * w.y + nn.z * w.z + nn.w * w.w;
    }
    // reduce across the 8 threads of each node (consecutive lanes)
#pragma unroll
    for (int off = 4; off; off >>= 1) {
        pc += __shfl_down_sync(0xffffffffu, pc, off, 8);
        nc += __shfl_down_sync(0xffffffffu, nc, off, 8);
        pg += __shfl_down_sync(0xffffffffu, pg, off, 8);
        ng += __shfl_down_sync(0xffffffffu, ng, off, 8);
    }
    if ((tid & 7) == 0) {
        const float inv = 0.5f / NN;
        contrib[node] = inv * (splus(-pg) + splus(ng)) + inv * (splus(-pc) + splus(nc));
    }
    __syncthreads();
    if (tid == 0) {
        float s = 0.f;
#pragma unroll
        for (int i = 0; i < 32; i++) s += contrib[i];
        g_partial[blockIdx.x] = s;
    }
}

__global__ void __launch_bounds__(256) k_loss_red(float* __restrict__ out) {
    __shared__ float sm[256];
    int t = threadIdx.x;
    float s = 0.f;
    for (int i = t; i < 625; i += 256) s += g_partial[i];
    sm[t] = s;
    __syncthreads();
    for (int off = 128; off >= 32; off >>= 1) {
        if (t < off) sm[t] += sm[t + off];
        __syncthreads();
    }
    if (t < 32) {
        float v = sm[t];
#pragma unroll
        for (int off = 16; off; off >>= 1) v += __shfl_down_sync(0xffffffffu, v, off);
        if (t == 0) out[0] = v;
    }
}

// ---------------- host driver ----------------
extern "C" void kernel_launch(void* const* d_in, const int* in_sizes, int n_in,
                              void* d_out, int out_size) {
    const float* features = (const float*)d_in[0];
    const float* W1       = (const float*)d_in[1];
    const float* b1       = (const float*)d_in[2];
    const float* W2       = (const float*)d_in[3];
    const float* b2       = (const float*)d_in[4];
    const float* disc_W   = (const float*)d_in[5];
    const float* cl_init  = (const float*)d_in[6];
    const int*   eidx     = (const int*)d_in[7];
    const int*   perm     = (const int*)d_in[8];
    float* out = (float*)d_out;

    int E = in_sizes[7] / 2;
    const int* src = eidx;
    const int* dst = eidx + E;

    float *agg, *hid, *pos, *neg, *data, *mu, *munorm;
    cudaGetSymbolAddress((void**)&agg, g_agg);
    cudaGetSymbolAddress((void**)&hid, g_hid);
    cudaGetSymbolAddress((void**)&pos, g_pos);
    cudaGetSymbolAddress((void**)&neg, g_neg);
    cudaGetSymbolAddress((void**)&data, g_data);
    cudaGetSymbolAddress((void**)&mu, g_mu);
    cudaGetSymbolAddress((void**)&munorm, g_munorm);

    // graph setup
    k_init<<<(NN + 255) / 256, 256>>>();
    k_count<<<(E + 255) / 256, 256>>>(src, dst, E);
    k_prep<<<1, 1024>>>();
    k_fillcsr<<<(E + 255) / 256, 256>>>(src, dst, E);

    dim3 ggrid(157, 4);
    // positive encoder pass
    k_aggregate<<<NN, 128>>>(features, nullptr, agg);
    k_gemm<<<ggrid, 256>>>(agg, W1, b1, hid, 1);
    k_aggregate<<<NN, 128>>>(hid, nullptr, agg);
    k_gemm<<<ggrid, 256>>>(agg, W2, b2, pos, 0);
    // negative (corrupted) encoder pass
    k_aggregate<<<NN, 128>>>(features, perm, agg);
    k_gemm<<<ggrid, 256>>>(agg, W1, b1, hid, 1);
    k_aggregate<<<NN, 128>>>(hid, nullptr, agg);
    k_gemm<<<ggrid, 256>>>(agg, W2, b2, neg, 0);

    // graph summary -> ws
    k_colsum_p1<<<NCB, 512>>>(pos);
    k_gs<<<1, 512>>>();
    k_ws<<<64, 256>>>(disc_W);

    // clusternet: 10 + 1 iterations
    k_rownorm<<<NN, 128>>>(pos, data, 1e-8f);
    k_copy<<<(KK * HH + 255) / 256, 256>>>(cl_init, mu, KK * HH);
    for (int it = 0; it < NITER; it++) {
        k_rownorm<<<KK, 128>>>(mu, munorm, 0.f);
        k_dist<<<NDB, 256>>>();
        k_colsum_red<<<1, 128>>>();
        k_mu<<<dim3(8, NSPLIT), 256>>>();
        k_mu_update<<<256, 256>>>();
    }

    // fused epilogue
    k_final<<<625, 256>>>();
    k_loss_red<<<1, 256>>>(out);
}

// round 7
// speedup vs baseline: 1.0081x; 1.0081x over previous
#include <cuda_runtime.h>
#include <math.h>

#define NN 20000
#define HH 512
#define KK 128
#define EMAX 340000
#define NITER 11
#define NSPLIT 25
#define CHUNK 800
#define NDB 313      // ceil(20000/64) dist blocks
#define NCB 157      // ceil(20000/128) colsum blocks

// ---------------- device scratch (static, no allocation) ----------------
__device__ int   g_deg_out[NN], g_deg_in[NN];
__device__ float g_inv_out[NN], g_inv_in[NN];
__device__ int   g_rowptr[NN + 1], g_cursor[NN];
__device__ int   g_colsrc[EMAX];
__device__ float g_agg[(size_t)NN * HH];
__device__ float g_hid[(size_t)NN * HH];
__device__ float g_pos[(size_t)NN * HH];
__device__ float g_neg[(size_t)NN * HH];
__device__ float g_data[(size_t)NN * HH];
__device__ float g_r[(size_t)NN * KK];
__device__ float g_mu[KK * HH], g_munorm[KK * HH];
__device__ float g_muacc_part[(size_t)NSPLIT * KK * HH];
__device__ float g_colsum_part[NDB * KK];
__device__ float g_colsum[KK];
__device__ float g_cspart[NCB * HH];
__device__ float g_gs[HH], g_ws[HH];
__device__ float g_partial[625];

__device__ __forceinline__ float splus(float x) {
    return (x > 0.f) ? (x + log1pf(expf(-x))) : log1pf(expf(x));
}
__device__ __forceinline__ float sigm(float x) { return 1.f / (1.f + expf(-x)); }

// ---------------- graph setup ----------------
__global__ void k_init() {
    int i = blockIdx.x * blockDim.x + threadIdx.x;
    if (i < NN) { g_deg_out[i] = 0; g_deg_in[i] = 0; }
}

__global__ void k_count(const int* __restrict__ src, const int* __restrict__ dst, int E) {
    int e = blockIdx.x * blockDim.x + threadIdx.x;
    if (e < E) {
        atomicAdd(&g_deg_out[src[e]], 1);
        atomicAdd(&g_deg_in[dst[e]], 1);
    }
}

// single block: inv-degree factors + exclusive scan of in-degrees -> CSR row_ptr
__global__ void k_prep() {
    int t = threadIdx.x;
    for (int i = t; i < NN; i += 1024) {
        g_inv_out[i] = rsqrtf((float)max(g_deg_out[i], 1));
        g_inv_in[i]  = rsqrtf((float)max(g_deg_in[i], 1));
    }
    __syncthreads();
    __shared__ int ssum[1024];
    const int CH = (NN + 1023) / 1024;   // 20
    int b = t * CH, e = min(b + CH, NN);
    int s = 0;
    for (int i = b; i < e; i++) s += g_deg_in[i];
    ssum[t] = s;
    __syncthreads();
    for (int off = 1; off < 1024; off <<= 1) {
        int v = (t >= off) ? ssum[t - off] : 0;
        __syncthreads();
        ssum[t] += v;
        __syncthreads();
    }
    int run = (t == 0) ? 0 : ssum[t - 1];
    for (int i = b; i < e; i++) {
        g_rowptr[i] = run; g_cursor[i] = run;
        run += g_deg_in[i];
    }
    if (t == 1023) g_rowptr[NN] = ssum[1023];
}

__global__ void k_fillcsr(const int* __restrict__ src, const int* __restrict__ dst, int E) {
    int e = blockIdx.x * blockDim.x + threadIdx.x;
    if (e < E) {
        int p = atomicAdd(&g_cursor[dst[e]], 1);
        g_colsrc[p] = src[e];
    }
}

// ---------------- GCN aggregation: out[i] = inv_in[i] * sum_{e:dst=i} inv_out[s]*X[map(s)]
__global__ void __launch_bounds__(128) k_aggregate(const float* __restrict__ X,
                                                   const int* __restrict__ perm,
                                                   float* __restrict__ out) {
    int i = blockIdx.x;
    int t = threadIdx.x;   // 128 threads, one float4 each over 512 cols
    int s0 = g_rowptr[i], s1 = g_rowptr[i + 1];
    float ax = 0.f, ay = 0.f, az = 0.f, aw = 0.f;
    for (int e = s0; e < s1; e++) {
        int s = g_colsrc[e];
        float w = g_inv_out[s];
        int row = perm ? perm[s] : s;
        float4 v = ((const float4*)(X + (size_t)row * HH))[t];
        ax = fmaf(w, v.x, ax); ay = fmaf(w, v.y, ay);
        az = fmaf(w, v.z, az); aw = fmaf(w, v.w, aw);
    }
    float wi = g_inv_in[i];
    ((float4*)(out + (size_t)i * HH))[t] = make_float4(ax * wi, ay * wi, az * wi, aw * wi);
}

// ---------------- dense GEMM: C[M,512] = A[M,512] @ W[512,512] + bias (opt relu)
__global__ void __launch_bounds__(256) k_gemm(const float* __restrict__ A,
                                              const float* __restrict__ W,
                                              const float* __restrict__ bias,
                                              float* __restrict__ C, int relu) {
    __shared__ __align__(16) float As[8][132];
    __shared__ __align__(16) float Bs[8][128];
    int tid = threadIdx.x;
    int bm = blockIdx.x * 128, bn = blockIdx.y * 128;
    int tx = tid & 15, ty = tid >> 4;
    float acc[8][8];
#pragma unroll
    for (int i = 0; i < 8; i++)
#pragma unroll
        for (int j = 0; j < 8; j++) acc[i][j] = 0.f;

    int lr = tid >> 1, lc = (tid & 1) * 4;
    int bkr = tid >> 5, bc4 = (tid & 31) * 4;
    int arow = bm + lr;
    const float* Aptr = A + (size_t)arow * HH + lc;
    const float* Wptr = W + (size_t)bkr * HH + bn + bc4;

    for (int k0 = 0; k0 < HH; k0 += 8) {
        float4 av = make_float4(0.f, 0.f, 0.f, 0.f);
        if (arow < NN) av = *(const float4*)(Aptr + k0);
        As[lc + 0][lr] = av.x; As[lc + 1][lr] = av.y;
        As[lc + 2][lr] = av.z; As[lc + 3][lr] = av.w;
        *(float4*)&Bs[bkr][bc4] = *(const float4*)(Wptr + (size_t)k0 * HH);
        __syncthreads();
#pragma unroll
        for (int kk = 0; kk < 8; kk++) {
            float4 a0 = *(float4*)&As[kk][ty * 8];
            float4 a1 = *(float4*)&As[kk][ty * 8 + 4];
            float4 b0 = *(float4*)&Bs[kk][tx * 8];
            float4 b1 = *(float4*)&Bs[kk][tx * 8 + 4];
            float aa[8] = {a0.x, a0.y, a0.z, a0.w, a1.x, a1.y, a1.z, a1.w};
            float bb[8] = {b0.x, b0.y, b0.z, b0.w, b1.x, b1.y, b1.z, b1.w};
#pragma unroll
            for (int i = 0; i < 8; i++)
#pragma unroll
                for (int j = 0; j < 8; j++)
                    acc[i][j] = fmaf(aa[i], bb[j], acc[i][j]);
        }
        __syncthreads();
    }
#pragma unroll
    for (int i = 0; i < 8; i++) {
        int row = bm + ty * 8 + i;
        if (row < NN) {
#pragma unroll
            for (int j = 0; j < 8; j++) {
                float v = acc[i][j] + bias[bn + tx * 8 + j];
                if (relu) v = fmaxf(v, 0.f);
                C[(size_t)row * HH + bn + tx * 8 + j] = v;
            }
        }
    }
}

// ---------------- graph summary: column sum partials then sigmoid(mean) ----------------
__global__ void __launch_bounds__(512) k_colsum_p1(const float* __restrict__ P) {
    int b = blockIdx.x, t = threadIdx.x;
    int r0 = b * 128, r1 = min(r0 + 128, NN);
    float s = 0.f;
    for (int r = r0; r < r1; r++) s += P[(size_t)r * HH + t];
    g_cspart[b * HH + t] = s;
}

__global__ void __launch_bounds__(512) k_gs() {
    int t = threadIdx.x;
    float s = 0.f;
    for (int b = 0; b < NCB; b++) s += g_cspart[b * HH + t];
    g_gs[t] = sigm(s * (1.0f / NN));
}

__global__ void __launch_bounds__(256) k_ws(const float* __restrict__ dW) {
    int t = threadIdx.x;
    int w = t >> 5, l = t & 31;
    int row = blockIdx.x * 8 + w;
    float s = 0.f;
#pragma unroll
    for (int q = 0; q < 16; q++) {
        int j = q * 32 + l;
        s += dW[(size_t)row * HH + j] * g_gs[j];
    }
#pragma unroll
    for (int off = 16; off; off >>= 1) s += __shfl_xor_sync(0xffffffffu, s, off);
    if (l == 0) g_ws[row] = s;
}

// ---------------- row normalize ----------------
__global__ void __launch_bounds__(128) k_rownorm(const float* __restrict__ in,
                                                 float* __restrict__ out, float eps) {
    int i = blockIdx.x, t = threadIdx.x;
    float4 v = ((const float4*)(in + (size_t)i * HH))[t];
    float ss = v.x * v.x + v.y * v.y + v.z * v.z + v.w * v.w;
#pragma unroll
    for (int off = 16; off; off >>= 1) ss += __shfl_xor_sync(0xffffffffu, ss, off);
    __shared__ float sw[4];
    if ((t & 31) == 0) sw[t >> 5] = ss;
    __syncthreads();
    float inv = 1.f / (sqrtf(sw[0] + sw[1] + sw[2] + sw[3]) + eps);
    ((float4*)(out + (size_t)i * HH))[t] =
        make_float4(v.x * inv, v.y * inv, v.z * inv, v.w * inv);
}

__global__ void k_copy(const float* __restrict__ s, float* __restrict__ d, int n) {
    int i = blockIdx.x * blockDim.x + threadIdx.x;
    if (i < n) d[i] = s[i];
}

// ---------------- fused dist + beta-softmax + colsum: r = softmax(100 * data@munorm^T)
__global__ void __launch_bounds__(256) k_dist() {
    __shared__ __align__(16) float As[16][68];
    __shared__ __align__(16) float Bs[16][132];
    __shared__ __align__(16) float sd[64][132];
    int tid = threadIdx.x;
    int n0 = blockIdx.x * 64;
    int rows_valid = min(64, NN - n0);
    int tx = tid & 15, ty = tid >> 4;
    float acc[4][8];
#pragma unroll
    for (int i = 0; i < 4; i++)
#pragma unroll
        for (int j = 0; j < 8; j++) acc[i][j] = 0.f;

    int ar = tid >> 2, ac4 = (tid & 3) * 4;
    bool avalid = (n0 + ar) < NN;
    const float* aptr = g_data + (size_t)(n0 + ar) * HH + ac4;

    for (int k0 = 0; k0 < HH; k0 += 16) {
        float4 av = avalid ? *(const float4*)(aptr + k0) : make_float4(0.f, 0.f, 0.f, 0.f);
        As[ac4 + 0][ar] = av.x; As[ac4 + 1][ar] = av.y;
        As[ac4 + 2][ar] = av.z; As[ac4 + 3][ar] = av.w;
#pragma unroll
        for (int l = 0; l < 2; l++) {
            int idx = tid + l * 256;
            int kc = idx >> 2, c4 = (idx & 3) * 4;
            float4 bv = *(const float4*)(g_munorm + (size_t)kc * HH + k0 + c4);
            Bs[c4 + 0][kc] = bv.x; Bs[c4 + 1][kc] = bv.y;
            Bs[c4 + 2][kc] = bv.z; Bs[c4 + 3][kc] = bv.w;
        }
        __syncthreads();
#pragma unroll
        for (int kk = 0; kk < 16; kk++) {
            float4 a = *(float4*)&As[kk][ty * 4];
            float4 b0 = *(float4*)&Bs[kk][tx * 8];
            float4 b1 = *(float4*)&Bs[kk][tx * 8 + 4];
            float aa[4] = {a.x, a.y, a.z, a.w};
            float bb[8] = {b0.x, b0.y, b0.z, b0.w, b1.x, b1.y, b1.z, b1.w};
#pragma unroll
            for (int i = 0; i < 4; i++)
#pragma unroll
                for (int j = 0; j < 8; j++)
                    acc[i][j] = fmaf(aa[i], bb[j], acc[i][j]);
        }
        __syncthreads();
    }
#pragma unroll
    for (int i = 0; i < 4; i++)
#pragma unroll
        for (int j = 0; j < 8; j++)
            sd[ty * 4 + i][tx * 8 + j] = acc[i][j];
    __syncthreads();

    // row softmax with temp 100: 4 threads per row, 32 cols each
    int r = tid >> 2, g = tid & 3;
    if (r < rows_valid) {
        float m = -1e30f;
#pragma unroll
        for (int q = 0; q < 32; q++) m = fmaxf(m, sd[r][g + 4 * q]);
        m = fmaxf(m, __shfl_xor_sync(0xffffffffu, m, 1, 4));
        m = fmaxf(m, __shfl_xor_sync(0xffffffffu, m, 2, 4));
        float s = 0.f;
#pragma unroll
        for (int q = 0; q < 32; q++) {
            float e = expf(100.0f * (sd[r][g + 4 * q] - m));
            sd[r][g + 4 * q] = e;
            s += e;
        }
        s += __shfl_xor_sync(0xffffffffu, s, 1, 4);
        s += __shfl_xor_sync(0xffffffffu, s, 2, 4);
        float inv = 1.f / s;
#pragma unroll
        for (int q = 0; q < 32; q++) sd[r][g + 4 * q] *= inv;
    }
    __syncthreads();

    // coalesced r write
    for (int q = 0; q < 32; q++) {
        int idx = tid + 256 * q;
        int row = idx >> 7, col = idx & 127;
        if (row < rows_valid) g_r[(size_t)(n0 + row) * KK + col] = sd[row][col];
    }
    // per-block column sums (deterministic partials)
    if (tid < 128) {
        float s = 0.f;
        for (int row = 0; row < rows_valid; row++) s += sd[row][tid];
        g_colsum_part[blockIdx.x * KK + tid] = s;
    }
}

__global__ void k_colsum_red() {
    int t = threadIdx.x;   // 128
    float s = 0.f;
    for (int b = 0; b < NDB; b++) s += g_colsum_part[b * KK + t];
    g_colsum[t] = s;
}

// ---------------- muacc partial GEMM: part[split] = r_chunk^T @ data_chunk
__global__ void __launch_bounds__(256) k_mu() {
    __shared__ __align__(16) float As[16][128];   // r[n][c]
    __shared__ __align__(16) float Bs[16][64];    // data[n][col]
    int tid = threadIdx.x;
    int colbase = blockIdx.x * 64;
    int split = blockIdx.y;
    int nbase = split * CHUNK;
    int tx = tid & 15, ty = tid >> 4;
    float acc[8][4];
#pragma unroll
    for (int i = 0; i < 8; i++)
#pragma unroll
        for (int j = 0; j < 4; j++) acc[i][j] = 0.f;

    int akk = tid >> 4, ac = (tid & 15) * 8;   // As: 2 float4
    int bkk = tid >> 4, bc = (tid & 15) * 4;   // Bs: 1 float4

    for (int n0 = nbase; n0 < nbase + CHUNK; n0 += 16) {
        *(float4*)&As[akk][ac]     = *(const float4*)(g_r + (size_t)(n0 + akk) * KK + ac);
        *(float4*)&As[akk][ac + 4] = *(const float4*)(g_r + (size_t)(n0 + akk) * KK + ac + 4);
        *(float4*)&Bs[bkk][bc]     = *(const float4*)(g_data + (size_t)(n0 + bkk) * HH + colbase + bc);
        __syncthreads();
#pragma unroll
        for (int kk = 0; kk < 16; kk++) {
            float4 b = *(float4*)&Bs[kk][tx * 4];
            float4 a0 = *(float4*)&As[kk][ty * 8];
            float4 a1 = *(float4*)&As[kk][ty * 8 + 4];
            float aa[8] = {a0.x, a0.y, a0.z, a0.w, a1.x, a1.y, a1.z, a1.w};
            float bb[4] = {b.x, b.y, b.z, b.w};
#pragma unroll
            for (int i = 0; i < 8; i++)
#pragma unroll
                for (int j = 0; j < 4; j++)
                    acc[i][j] = fmaf(aa[i], bb[j], acc[i][j]);
        }
        __syncthreads();
    }
#pragma unroll
    for (int i = 0; i < 8; i++) {
        int c = ty * 8 + i;
#pragma unroll
        for (int j = 0; j < 4; j++)
            g_muacc_part[((size_t)split * KK + c) * HH + colbase + tx * 4 + j] = acc[i][j];
    }
}

__global__ void __launch_bounds__(256) k_mu_update() {
    int e = blockIdx.x * 256 + threadIdx.x;   // 65536 total
    int c = e >> 9, j = e & 511;
    float s = 0.f;
#pragma unroll 5
    for (int sp = 0; sp < NSPLIT; sp++)
        s += g_muacc_part[((size_t)sp * KK + c) * HH + j];
    g_mu[c * HH + j] = s / g_colsum[c];
}

// ---------------- fused epilogue: cs = sigmoid(r@mu); dots + softplus means ----------------
__global__ void __launch_bounds__(256) k_final() {
    __shared__ __align__(16) float r_s[32][128];
    __shared__ __align__(16) float mu_s[128][36];
    __shared__ float ws_s[HH];
    __shared__ float contrib[32];
    int tid = threadIdx.x;
    int n0 = blockIdx.x * 32;
    // load r rows
#pragma unroll
    for (int q = 0; q < 4; q++) {
        int i4 = tid + 256 * q;                 // 1024 float4s = 32*128/4
        int row = i4 >> 5, cp = (i4 & 31) * 4;
        *(float4*)&r_s[row][cp] = *(const float4*)(g_r + (size_t)(n0 + row) * KK + cp);
    }
    ws_s[tid] = g_ws[tid];
    ws_s[tid + 256] = g_ws[tid + 256];

    int node = tid >> 3, cg = (tid & 7) * 4;
    float pc = 0.f, nc = 0.f, pg = 0.f, ng = 0.f;

    for (int tile = 0; tile < 16; tile++) {
        __syncthreads();
        // load mu tile [128 x 32]
#pragma unroll
        for (int q = 0; q < 4; q++) {
            int i4 = tid + 256 * q;             // 1024 float4s
            int k = i4 >> 3, cp = (i4 & 7) * 4;
            *(float4*)&mu_s[k][cp] = *(const float4*)(g_mu + (size_t)k * HH + tile * 32 + cp);
        }
        __syncthreads();
        float c0 = 0.f, c1 = 0.f, c2 = 0.f, c3 = 0.f;
#pragma unroll 8
        for (int k = 0; k < 128; k++) {
            float rv = r_s[node][k];
            float4 m = *(float4*)&mu_s[k][cg];
            c0 = fmaf(rv, m.x, c0); c1 = fmaf(rv, m.y, c1);
            c2 = fmaf(rv, m.z, c2); c3 = fmaf(rv, m.w, c3);
        }
        int col = tile * 32 + cg;
        float4 p = *(const float4*)(g_pos + (size_t)(n0 + node) * HH + col);
        float4 nn = *(const float4*)(g_neg + (size_t)(n0 + node) * HH + col);
        float4 w = *(float4*)&ws_s[col];
        float s0 = sigm(c0), s1 = sigm(c1), s2 = sigm(c2), s3 = sigm(c3);
        pc += s0 * p.x + s1 * p.y + s2 * p.z + s3 * p.w;
        nc += s0 * nn.x + s1 * nn.y + s2 * nn.z + s3 * nn.w;
        pg += p.x * w.x + p.y * w.y + p.z * w.z + p.w * w.w;
        ng += nn.x * w.x + nn.y * w.y + nn.z * w.z + nn.w * w.w;
    }
    // reduce across the 8 threads of each node (consecutive lanes)
#pragma unroll
    for (int off = 4; off; off >>= 1) {
        pc += __shfl_down_sync(0xffffffffu, pc, off, 8);
        nc += __shfl_down_sync(0xffffffffu, nc, off, 8);
        pg += __shfl_down_sync(0xffffffffu, pg, off, 8);
        ng += __shfl_down_sync(0xffffffffu, ng, off, 8);
    }
    if ((tid & 7) == 0) {
        const float inv = 0.5f / NN;
        contrib[node] = inv * (splus(-pg) + splus(ng)) + inv * (splus(-pc) + splus(nc));
    }
    __syncthreads();
    if (tid == 0) {
        float s = 0.f;
#pragma unroll
        for (int i = 0; i < 32; i++) s += contrib[i];
        g_partial[blockIdx.x] = s;
    }
}

__global__ void __launch_bounds__(256) k_loss_red(float* __restrict__ out) {
    __shared__ float sm[256];
    int t = threadIdx.x;
    float s = 0.f;
    for (int i = t; i < 625; i += 256) s += g_partial[i];
    sm[t] = s;
    __syncthreads();
    for (int off = 128; off >= 32; off >>= 1) {
        if (t < off) sm[t] += sm[t + off];
        __syncthreads();
    }
    if (t < 32) {
        float v = sm[t];
#pragma unroll
        for (int off = 16; off; off >>= 1) v += __shfl_down_sync(0xffffffffu, v, off);
        if (t == 0) out[0] = v;
    }
}

// ---------------- host driver ----------------
extern "C" void kernel_launch(void* const* d_in, const int* in_sizes, int n_in,
                              void* d_out, int out_size) {
    const float* features = (const float*)d_in[0];
    const float* W1       = (const float*)d_in[1];
    const float* b1       = (const float*)d_in[2];
    const float* W2       = (const float*)d_in[3];
    const float* b2       = (const float*)d_in[4];
    const float* disc_W   = (const float*)d_in[5];
    const float* cl_init  = (const float*)d_in[6];
    const int*   eidx     = (const int*)d_in[7];
    const int*   perm     = (const int*)d_in[8];
    float* out = (float*)d_out;

    int E = in_sizes[7] / 2;
    const int* src = eidx;
    const int* dst = eidx + E;

    float *agg, *hid, *pos, *neg, *data, *mu, *munorm;
    cudaGetSymbolAddress((void**)&agg, g_agg);
    cudaGetSymbolAddress((void**)&hid, g_hid);
    cudaGetSymbolAddress((void**)&pos, g_pos);
    cudaGetSymbolAddress((void**)&neg, g_neg);
    cudaGetSymbolAddress((void**)&data, g_data);
    cudaGetSymbolAddress((void**)&mu, g_mu);
    cudaGetSymbolAddress((void**)&munorm, g_munorm);

    // graph setup
    k_init<<<(NN + 255) / 256, 256>>>();
    k_count<<<(E + 255) / 256, 256>>>(src, dst, E);
    k_prep<<<1, 1024>>>();
    k_fillcsr<<<(E + 255) / 256, 256>>>(src, dst, E);

    dim3 ggrid(157, 4);
    // positive encoder pass
    k_aggregate<<<NN, 128>>>(features, nullptr, agg);
    k_gemm<<<ggrid, 256>>>(agg, W1, b1, hid, 1);
    k_aggregate<<<NN, 128>>>(hid, nullptr, agg);
    k_gemm<<<ggrid, 256>>>(agg, W2, b2, pos, 0);
    // negative (corrupted) encoder pass
    k_aggregate<<<NN, 128>>>(features, perm, agg);
    k_gemm<<<ggrid, 256>>>(agg, W1, b1, hid, 1);
    k_aggregate<<<NN, 128>>>(hid, nullptr, agg);
    k_gemm<<<ggrid, 256>>>(agg, W2, b2, neg, 0);

    // graph summary -> ws
    k_colsum_p1<<<NCB, 512>>>(pos);
    k_gs<<<1, 512>>>();
    k_ws<<<64, 256>>>(disc_W);

    // clusternet: 10 + 1 iterations
    k_rownorm<<<NN, 128>>>(pos, data, 1e-8f);
    k_copy<<<(KK * HH + 255) / 256, 256>>>(cl_init, mu, KK * HH);
    for (int it = 0; it < NITER; it++) {
        k_rownorm<<<KK, 128>>>(mu, munorm, 0.f);
        k_dist<<<NDB, 256>>>();
        k_colsum_red<<<1, 128>>>();
        k_mu<<<dim3(8, NSPLIT), 256>>>();
        k_mu_update<<<256, 256>>>();
    }

    // fused epilogue
    k_final<<<625, 256>>>();
    k_loss_red<<<1, 256>>>(out);
}